// round 14
// baseline (speedup 1.0000x reference)
#include <cuda_runtime.h>
#include <cstdint>

#define NUM_E 64
#define DIM 512
#define NTOK 131072
#define CAP 3072

#define BM 128
#define BN 128
#define BK 32
#define NCHUNK 16            // 512 / 32
#define NSTAGE 3
#define MTILES (CAP / BM)    // 24
#define NTILES (DIM / BN)    // 4
#define TOTAL_TILES (MTILES * NTILES * NUM_E)   // 6144
#define NCTA 296             // 2 per SM x 148 SMs

#define ROW_STRIDE 144       // bytes per smem row: 32 fp32 = 128B data + 16 pad
#define A_TILE_BYTES (BM * ROW_STRIDE)        // 18432
#define B_TILE_BYTES (BN * ROW_STRIDE)        // 18432 (n-major: 128 n-rows x 32 k)
#define STAGE_BYTES (A_TILE_BYTES + B_TILE_BYTES)   // 36864
#define SMEM_TOTAL (NSTAGE * STAGE_BYTES)     // 110592; x2 CTAs = 221184 <= 228KB

__device__ int g_off[NUM_E];
__device__ int g_ctr;
__device__ float g_wt[(size_t)NUM_E * DIM * DIM];   // W transposed [e][n][k], tf32-rounded

// ---------------- helpers ----------------
__device__ __forceinline__ uint32_t smem_u32(const void* p) {
    uint32_t a;
    asm("{ .reg .u64 t; cvta.to.shared.u64 t, %1; cvt.u32.u64 %0, t; }" : "=r"(a) : "l"(p));
    return a;
}

__device__ __forceinline__ void cp16(uint32_t dst, const void* src, bool pred) {
    int sz = pred ? 16 : 0;
    asm volatile("cp.async.cg.shared.global [%0], [%1], 16, %2;"
        :: "r"(dst), "l"(src), "r"(sz) : "memory");
}

__device__ __forceinline__ void ldsm_x4(uint32_t* r, uint32_t addr) {
    asm volatile("ldmatrix.sync.aligned.m8n8.x4.shared.b16 {%0,%1,%2,%3}, [%4];"
        : "=r"(r[0]), "=r"(r[1]), "=r"(r[2]), "=r"(r[3]) : "r"(addr));
}

// m16n8k8 tf32: A 4 regs, B 2 regs, C 4 fp32
__device__ __forceinline__ void mma_tf32(float* c, const uint32_t* a,
                                         uint32_t b0, uint32_t b1) {
    asm volatile(
        "mma.sync.aligned.m16n8k8.row.col.f32.tf32.tf32.f32 "
        "{%0,%1,%2,%3}, {%4,%5,%6,%7}, {%8,%9}, {%0,%1,%2,%3};"
        : "+f"(c[0]), "+f"(c[1]), "+f"(c[2]), "+f"(c[3])
        : "r"(a[0]), "r"(a[1]), "r"(a[2]), "r"(a[3]), "r"(b0), "r"(b1));
}

// ---------------- small kernels ----------------
__global__ void scan_kernel(const int* __restrict__ sizes) {
    __shared__ int s[NUM_E];
    int t = threadIdx.x;
    s[t] = sizes[t];
    __syncthreads();
    if (t == 0) {
        int acc = 0;
        #pragma unroll
        for (int i = 0; i < NUM_E; i++) { int v = s[i]; s[i] = acc; acc += v; }
        g_ctr = 0;          // reset persistent-kernel work counter
    }
    __syncthreads();
    g_off[t] = s[t];
}

// W[e][k][n] fp32 -> Wt[e][n][k] tf32-rounded fp32
__global__ void convert_w(const float* __restrict__ w) {
    __shared__ float t[32][33];
    const int e = blockIdx.z;
    const int k0 = blockIdx.x * 32, n0 = blockIdx.y * 32;
    const float* W = w + (size_t)e * DIM * DIM;
    #pragma unroll
    for (int p = 0; p < 32; p += 8)
        t[threadIdx.y + p][threadIdx.x] = W[(size_t)(k0 + threadIdx.y + p) * DIM + n0 + threadIdx.x];
    __syncthreads();
    #pragma unroll
    for (int p = 0; p < 32; p += 8) {
        int n = n0 + threadIdx.y + p;
        int k = k0 + threadIdx.x;
        float v = t[threadIdx.x][threadIdx.y + p];
        uint32_t r;
        asm volatile("cvt.rna.tf32.f32 %0, %1;" : "=r"(r) : "f"(v));
        g_wt[(size_t)e * DIM * DIM + (size_t)n * DIM + k] = __uint_as_float(r);
    }
}

// ---------------- grouped GEMM (persistent) ----------------
__device__ __forceinline__ void load_stage(uint32_t smem_base, int stage, int c,
                                           long tok_base, int e, int col0, int tid,
                                           const float* __restrict__ inputs) {
    const int kk = c * BK;
    const uint32_t sA = smem_base + stage * STAGE_BYTES;
    const uint32_t sB = sA + A_TILE_BYTES;
    // A: 128 m-rows x 128B data (8 x 16B chunks), stride 144B
    #pragma unroll
    for (int i = tid; i < 1024; i += 256) {
        int r = i >> 3, ch = i & 7;
        long tok = tok_base + r;
        bool v = tok < (long)NTOK;
        const float* g = inputs + (v ? ((size_t)tok * DIM + kk + ch * 4) : 0);
        cp16(sA + (uint32_t)(r * ROW_STRIDE + ch * 16), g, v);
    }
    // B: 128 n-rows x 128B data (8 x 16B chunks of k), stride 144B, from Wt[e][n][k]
    #pragma unroll
    for (int i = tid; i < 1024; i += 256) {
        int r = i >> 3, ch = i & 7;
        const float* g = g_wt + (size_t)e * DIM * DIM + (size_t)(col0 + r) * DIM + kk + ch * 4;
        cp16(sB + (uint32_t)(r * ROW_STRIDE + ch * 16), g, true);
    }
    asm volatile("cp.async.commit_group;" ::: "memory");
}

__global__ __launch_bounds__(256, 2)
void grouped_gemm(const int* __restrict__ sizes,
                  const float* __restrict__ inputs,
                  float* __restrict__ out) {
    extern __shared__ char smem[];
    __shared__ int s_tile;

    const uint32_t smem_base = smem_u32(smem);
    const int tid = threadIdx.x;
    const int wid = tid >> 5;
    const int lane = tid & 31;
    const int wm = wid & 3;       // 4 warps along M: 32 rows each
    const int wn = wid >> 2;      // 2 warps along N: 64 cols each
    const int g = lane >> 2;      // group 0..7
    const int t = lane & 3;       // thread-in-group 0..3

    // ldmatrix lane-address components
    const int a_row  = lane & 15;
    const int a_koff = (lane >> 4) * 4;
    const int b_m    = lane >> 3;
    const int b_row  = ((b_m >> 1) * 8) + (lane & 7);
    const int b_koff = (b_m & 1) * 4;

    for (;;) {
        if (tid == 0) s_tile = atomicAdd(&g_ctr, 1);
        __syncthreads();
        const int tile = s_tile;
        if (tile >= TOTAL_TILES) return;

        // decode: m fastest (L2 locality), then n, then expert
        const int m  = tile % MTILES;
        const int n  = (tile / MTILES) % NTILES;
        const int e  = tile / (MTILES * NTILES);
        const int size = sizes[e];
        const int row0 = m * BM;
        // ensure prior tile's cp.async groups are retired before reusing smem
        if (row0 >= size) { asm volatile("cp.async.wait_group 0;" ::: "memory"); __syncthreads(); continue; }
        const int col0 = n * BN;
        const long tok_base = (long)g_off[e] + row0;

        float acc[2][8][4];
        #pragma unroll
        for (int mt = 0; mt < 2; mt++)
            #pragma unroll
            for (int nt = 0; nt < 8; nt++)
                #pragma unroll
                for (int q = 0; q < 4; q++) acc[mt][nt][q] = 0.f;

        // prologue: depth-2 prefetch
        load_stage(smem_base, 0, 0, tok_base, e, col0, tid, inputs);
        load_stage(smem_base, 1, 1, tok_base, e, col0, tid, inputs);

        for (int c = 0; c < NCHUNK; c++) {
            if (c == NCHUNK - 1) asm volatile("cp.async.wait_group 0;" ::: "memory");
            else                 asm volatile("cp.async.wait_group 1;" ::: "memory");
            __syncthreads();
            if (c + 2 < NCHUNK)
                load_stage(smem_base, (c + 2) % NSTAGE, c + 2, tok_base, e, col0, tid, inputs);

            const uint32_t sA = smem_base + (c % NSTAGE) * STAGE_BYTES;
            const uint32_t sB = sA + A_TILE_BYTES;

            #pragma unroll
            for (int ks = 0; ks < 4; ks++) {
                uint32_t a[2][4];
                #pragma unroll
                for (int mt = 0; mt < 2; mt++) {
                    uint32_t addr = sA + (uint32_t)((wm * 32 + mt * 16 + a_row) * ROW_STRIDE
                                                    + (ks * 8 + a_koff) * 4);
                    ldsm_x4(a[mt], addr);
                }
                #pragma unroll
                for (int p = 0; p < 4; p++) {
                    uint32_t addr = sB + (uint32_t)((wn * 64 + p * 16 + b_row) * ROW_STRIDE
                                                    + (ks * 8 + b_koff) * 4);
                    uint32_t b[4];
                    ldsm_x4(b, addr);
                    mma_tf32(acc[0][2 * p],     a[0], b[0], b[1]);
                    mma_tf32(acc[1][2 * p],     a[1], b[0], b[1]);
                    mma_tf32(acc[0][2 * p + 1], a[0], b[2], b[3]);
                    mma_tf32(acc[1][2 * p + 1], a[1], b[2], b[3]);
                }
            }
        }

        // ---- epilogue ----
        #pragma unroll
        for (int mt = 0; mt < 2; mt++) {
            int r_lo = wm * 32 + mt * 16 + g;
            int r_hi = r_lo + 8;
            bool v_lo = (row0 + r_lo) < size;
            bool v_hi = (row0 + r_hi) < size;
            float* p_lo = out + (size_t)(tok_base + r_lo) * DIM + col0;
            float* p_hi = out + (size_t)(tok_base + r_hi) * DIM + col0;
            #pragma unroll
            for (int nt = 0; nt < 8; nt++) {
                int cidx = wn * 64 + nt * 8 + t * 2;
                if (v_lo) *(float2*)(p_lo + cidx) = make_float2(acc[mt][nt][0], acc[mt][nt][1]);
                if (v_hi) *(float2*)(p_hi + cidx) = make_float2(acc[mt][nt][2], acc[mt][nt][3]);
            }
        }
        __syncthreads();   // all warps done reading smem before next tile's prologue
    }
}

// ---------------- launch ----------------
extern "C" void kernel_launch(void* const* d_in, const int* in_sizes, int n_in,
                              void* d_out, int out_size) {
    const float* inputs = (const float*)d_in[0];
    const int*   sizes  = (const int*)  d_in[1];
    const float* weight = (const float*)d_in[2];
    float*       out    = (float*)d_out;

    cudaFuncSetAttribute(grouped_gemm, cudaFuncAttributeMaxDynamicSharedMemorySize, SMEM_TOTAL);

    // Order: convert_w, scan, gemm — so ncu (-s 5 -c 1) lands on grouped_gemm
    convert_w<<<dim3(16, 16, 64), dim3(32, 8)>>>(weight);
    scan_kernel<<<1, NUM_E>>>(sizes);
    grouped_gemm<<<NCTA, 256, SMEM_TOTAL>>>(sizes, inputs, out);
}

// round 15
// speedup vs baseline: 1.0170x; 1.0170x over previous
#include <cuda_runtime.h>
#include <cstdint>

#define NUM_E 64
#define DIM 512
#define NTOK 131072
#define CAP 3072

#define BM 128
#define BN 128
#define BK 32
#define NCHUNK 16            // 512 / 32
#define NSTAGE 3

#define ROW_STRIDE 144       // bytes per smem row: 32 fp32 = 128B data + 16 pad
#define A_TILE_BYTES (BM * ROW_STRIDE)        // 18432
#define B_TILE_BYTES (BN * ROW_STRIDE)        // 18432 (n-major: 128 n-rows x 32 k)
#define STAGE_BYTES (A_TILE_BYTES + B_TILE_BYTES)   // 36864
#define SMEM_TOTAL (NSTAGE * STAGE_BYTES)     // 110592; x2 CTAs = 221184 <= 228KB

__device__ int g_off[NUM_E];
__device__ float g_wt[(size_t)NUM_E * DIM * DIM];   // W transposed [e][n][k], tf32-rounded

// ---------------- helpers ----------------
__device__ __forceinline__ uint32_t smem_u32(const void* p) {
    uint32_t a;
    asm("{ .reg .u64 t; cvta.to.shared.u64 t, %1; cvt.u32.u64 %0, t; }" : "=r"(a) : "l"(p));
    return a;
}

__device__ __forceinline__ void cp16(uint32_t dst, const void* src, bool pred) {
    int sz = pred ? 16 : 0;
    asm volatile("cp.async.cg.shared.global [%0], [%1], 16, %2;"
        :: "r"(dst), "l"(src), "r"(sz) : "memory");
}

__device__ __forceinline__ void ldsm_x4(uint32_t* r, uint32_t addr) {
    asm volatile("ldmatrix.sync.aligned.m8n8.x4.shared.b16 {%0,%1,%2,%3}, [%4];"
        : "=r"(r[0]), "=r"(r[1]), "=r"(r[2]), "=r"(r[3]) : "r"(addr));
}

// m16n8k8 tf32: A 4 regs, B 2 regs, C 4 fp32
__device__ __forceinline__ void mma_tf32(float* c, const uint32_t* a,
                                         uint32_t b0, uint32_t b1) {
    asm volatile(
        "mma.sync.aligned.m16n8k8.row.col.f32.tf32.tf32.f32 "
        "{%0,%1,%2,%3}, {%4,%5,%6,%7}, {%8,%9}, {%0,%1,%2,%3};"
        : "+f"(c[0]), "+f"(c[1]), "+f"(c[2]), "+f"(c[3])
        : "r"(a[0]), "r"(a[1]), "r"(a[2]), "r"(a[3]), "r"(b0), "r"(b1));
}

// ---------------- prep: W transpose+round AND expert-offset scan ----------------
// W[e][k][n] fp32 -> Wt[e][n][k] tf32-rounded fp32; block (0,0,0) also scans sizes.
__global__ void prep_kernel(const float* __restrict__ w, const int* __restrict__ sizes) {
    __shared__ float t[32][33];
    const int e = blockIdx.z;
    const int k0 = blockIdx.x * 32, n0 = blockIdx.y * 32;

    if (blockIdx.x == 0 && blockIdx.y == 0 && blockIdx.z == 0 &&
        threadIdx.x == 0 && threadIdx.y == 0) {
        int acc = 0;
        #pragma unroll
        for (int i = 0; i < NUM_E; i++) { int v = sizes[i]; g_off[i] = acc; acc += v; }
    }

    const float* W = w + (size_t)e * DIM * DIM;
    #pragma unroll
    for (int p = 0; p < 32; p += 8)
        t[threadIdx.y + p][threadIdx.x] = W[(size_t)(k0 + threadIdx.y + p) * DIM + n0 + threadIdx.x];
    __syncthreads();
    #pragma unroll
    for (int p = 0; p < 32; p += 8) {
        int n = n0 + threadIdx.y + p;
        int k = k0 + threadIdx.x;
        float v = t[threadIdx.x][threadIdx.y + p];
        uint32_t r;
        asm volatile("cvt.rna.tf32.f32 %0, %1;" : "=r"(r) : "f"(v));
        g_wt[(size_t)e * DIM * DIM + (size_t)n * DIM + k] = __uint_as_float(r);
    }
}

// ---------------- grouped GEMM ----------------
__device__ __forceinline__ void load_stage(uint32_t smem_base, int stage, int c,
                                           long tok_base, int e, int col0, int tid,
                                           const float* __restrict__ inputs) {
    const int kk = c * BK;
    const uint32_t sA = smem_base + stage * STAGE_BYTES;
    const uint32_t sB = sA + A_TILE_BYTES;
    // A: 128 m-rows x 128B data (8 x 16B chunks), stride 144B
    #pragma unroll
    for (int i = tid; i < 1024; i += 256) {
        int r = i >> 3, ch = i & 7;
        long tok = tok_base + r;
        bool v = tok < (long)NTOK;
        const float* g = inputs + (v ? ((size_t)tok * DIM + kk + ch * 4) : 0);
        cp16(sA + (uint32_t)(r * ROW_STRIDE + ch * 16), g, v);
    }
    // B: 128 n-rows x 128B data (8 x 16B chunks of k), stride 144B, from Wt[e][n][k]
    #pragma unroll
    for (int i = tid; i < 1024; i += 256) {
        int r = i >> 3, ch = i & 7;
        const float* g = g_wt + (size_t)e * DIM * DIM + (size_t)(col0 + r) * DIM + kk + ch * 4;
        cp16(sB + (uint32_t)(r * ROW_STRIDE + ch * 16), g, true);
    }
    asm volatile("cp.async.commit_group;" ::: "memory");
}

__global__ __launch_bounds__(256, 2)
void grouped_gemm(const int* __restrict__ sizes,
                  const float* __restrict__ inputs,
                  float* __restrict__ out) {
    extern __shared__ char smem[];
    const int e = blockIdx.z;
    const int size = sizes[e];
    const int row0 = blockIdx.x * BM;
    if (row0 >= size) return;
    const int col0 = blockIdx.y * BN;
    const long tok_base = (long)g_off[e] + row0;

    const uint32_t smem_base = smem_u32(smem);
    const int tid = threadIdx.x;
    const int wid = tid >> 5;
    const int lane = tid & 31;
    const int wm = wid & 3;       // 4 warps along M: 32 rows each
    const int wn = wid >> 2;      // 2 warps along N: 64 cols each
    const int g = lane >> 2;      // group 0..7
    const int t = lane & 3;       // thread-in-group 0..3

    // ldmatrix lane-address components
    const int a_row  = lane & 15;            // row within 16-row fragment
    const int a_koff = (lane >> 4) * 4;      // fp32 k-offset 0 or 4
    const int b_m    = lane >> 3;            // matrix index 0..3
    const int b_row  = ((b_m >> 1) * 8) + (lane & 7);   // n-row within 16-row pair
    const int b_koff = (b_m & 1) * 4;        // fp32 k-offset 0 or 4

    float acc[2][8][4];
    #pragma unroll
    for (int mt = 0; mt < 2; mt++)
        #pragma unroll
        for (int nt = 0; nt < 8; nt++)
            #pragma unroll
            for (int q = 0; q < 4; q++) acc[mt][nt][q] = 0.f;

    // prologue: depth-2 prefetch
    load_stage(smem_base, 0, 0, tok_base, e, col0, tid, inputs);
    load_stage(smem_base, 1, 1, tok_base, e, col0, tid, inputs);

    for (int c = 0; c < NCHUNK; c++) {
        if (c == NCHUNK - 1) asm volatile("cp.async.wait_group 0;" ::: "memory");
        else                 asm volatile("cp.async.wait_group 1;" ::: "memory");
        // single barrier: publishes chunk c AND protects stage (c+2)%3 (read in c-1)
        __syncthreads();
        if (c + 2 < NCHUNK)
            load_stage(smem_base, (c + 2) % NSTAGE, c + 2, tok_base, e, col0, tid, inputs);

        const uint32_t sA = smem_base + (c % NSTAGE) * STAGE_BYTES;
        const uint32_t sB = sA + A_TILE_BYTES;

        #pragma unroll
        for (int ks = 0; ks < 4; ks++) {
            // A fragments: one ldmatrix.x4 per mt; raw fp32 bits — TF32 MMA uses top 19 bits
            uint32_t a[2][4];
            #pragma unroll
            for (int mt = 0; mt < 2; mt++) {
                uint32_t addr = sA + (uint32_t)((wm * 32 + mt * 16 + a_row) * ROW_STRIDE
                                                + (ks * 8 + a_koff) * 4);
                ldsm_x4(a[mt], addr);
            }
            // B: one ldmatrix.x4 per 16-col pair p covers nt=2p (r0,r1) and nt=2p+1 (r2,r3)
            #pragma unroll
            for (int p = 0; p < 4; p++) {
                uint32_t addr = sB + (uint32_t)((wn * 64 + p * 16 + b_row) * ROW_STRIDE
                                                + (ks * 8 + b_koff) * 4);
                uint32_t b[4];
                ldsm_x4(b, addr);       // pre-rounded (rna) in prep_kernel
                mma_tf32(acc[0][2 * p],     a[0], b[0], b[1]);
                mma_tf32(acc[1][2 * p],     a[1], b[0], b[1]);
                mma_tf32(acc[0][2 * p + 1], a[0], b[2], b[3]);
                mma_tf32(acc[1][2 * p + 1], a[1], b[2], b[3]);
            }
        }
    }

    // ---- epilogue: c0=[g][2t] c1=[g][2t+1] c2=[g+8][2t] c3=[g+8][2t+1]
    #pragma unroll
    for (int mt = 0; mt < 2; mt++) {
        int r_lo = wm * 32 + mt * 16 + g;
        int r_hi = r_lo + 8;
        bool v_lo = (row0 + r_lo) < size;
        bool v_hi = (row0 + r_hi) < size;
        float* p_lo = out + (size_t)(tok_base + r_lo) * DIM + col0;
        float* p_hi = out + (size_t)(tok_base + r_hi) * DIM + col0;
        #pragma unroll
        for (int nt = 0; nt < 8; nt++) {
            int cidx = wn * 64 + nt * 8 + t * 2;
            if (v_lo) *(float2*)(p_lo + cidx) = make_float2(acc[mt][nt][0], acc[mt][nt][1]);
            if (v_hi) *(float2*)(p_hi + cidx) = make_float2(acc[mt][nt][2], acc[mt][nt][3]);
        }
    }
}

// ---------------- launch ----------------
extern "C" void kernel_launch(void* const* d_in, const int* in_sizes, int n_in,
                              void* d_out, int out_size) {
    const float* inputs = (const float*)d_in[0];
    const int*   sizes  = (const int*)  d_in[1];
    const float* weight = (const float*)d_in[2];
    float*       out    = (float*)d_out;

    cudaFuncSetAttribute(grouped_gemm, cudaFuncAttributeMaxDynamicSharedMemorySize, SMEM_TOTAL);

    // 2 launches per call (matches the R2/R9 structure where ncu profiled the GEMM)
    prep_kernel<<<dim3(16, 16, 64), dim3(32, 8)>>>(weight, sizes);
    grouped_gemm<<<dim3(CAP / BM, DIM / BN, NUM_E), 256, SMEM_TOTAL>>>(sizes, inputs, out);
}

// round 16
// speedup vs baseline: 1.0478x; 1.0302x over previous
#include <cuda_runtime.h>
#include <cstdint>

#define NUM_E 64
#define DIM 512
#define NTOK 131072
#define CAP 3072

#define BM 128
#define BN 128
#define BK 32
#define NCHUNK 16            // 512 / 32
#define NSTAGE 3

#define ROW_STRIDE 144       // bytes per smem row: 32 fp32 = 128B data + 16 pad
#define A_TILE_BYTES (BM * ROW_STRIDE)        // 18432
#define B_TILE_BYTES (BN * ROW_STRIDE)        // 18432 (n-major: 128 n-rows x 32 k)
#define STAGE_BYTES (A_TILE_BYTES + B_TILE_BYTES)   // 36864
#define SMEM_TOTAL (NSTAGE * STAGE_BYTES)     // 110592; x2 CTAs = 221184 <= 228KB

__device__ int g_off[NUM_E];
__device__ float g_wt[(size_t)NUM_E * DIM * DIM];   // W transposed [e][n][k], tf32-rounded

// ---------------- helpers ----------------
__device__ __forceinline__ uint32_t smem_u32(const void* p) {
    uint32_t a;
    asm("{ .reg .u64 t; cvta.to.shared.u64 t, %1; cvt.u32.u64 %0, t; }" : "=r"(a) : "l"(p));
    return a;
}

__device__ __forceinline__ void cp16(uint32_t dst, const void* src, bool pred) {
    int sz = pred ? 16 : 0;
    asm volatile("cp.async.cg.shared.global [%0], [%1], 16, %2;"
        :: "r"(dst), "l"(src), "r"(sz) : "memory");
}

__device__ __forceinline__ void ldsm_x4(uint32_t* r, uint32_t addr) {
    asm volatile("ldmatrix.sync.aligned.m8n8.x4.shared.b16 {%0,%1,%2,%3}, [%4];"
        : "=r"(r[0]), "=r"(r[1]), "=r"(r[2]), "=r"(r[3]) : "r"(addr));
}

// m16n8k8 tf32: A 4 regs, B 2 regs, C 4 fp32
__device__ __forceinline__ void mma_tf32(float* c, const uint32_t* a,
                                         uint32_t b0, uint32_t b1) {
    asm volatile(
        "mma.sync.aligned.m16n8k8.row.col.f32.tf32.tf32.f32 "
        "{%0,%1,%2,%3}, {%4,%5,%6,%7}, {%8,%9}, {%0,%1,%2,%3};"
        : "+f"(c[0]), "+f"(c[1]), "+f"(c[2]), "+f"(c[3])
        : "r"(a[0]), "r"(a[1]), "r"(a[2]), "r"(a[3]), "r"(b0), "r"(b1));
}

// ---------------- prep: W transpose+round AND expert-offset scan ----------------
// W[e][k][n] fp32 -> Wt[e][n][k] tf32-rounded fp32; block (0,0,0) also scans sizes.
__global__ void prep_kernel(const float* __restrict__ w, const int* __restrict__ sizes) {
    __shared__ float t[32][33];
    const int e = blockIdx.z;
    const int k0 = blockIdx.x * 32, n0 = blockIdx.y * 32;

    if (blockIdx.x == 0 && blockIdx.y == 0 && blockIdx.z == 0 &&
        threadIdx.x == 0 && threadIdx.y == 0) {
        int acc = 0;
        #pragma unroll
        for (int i = 0; i < NUM_E; i++) { int v = sizes[i]; g_off[i] = acc; acc += v; }
    }

    const float* W = w + (size_t)e * DIM * DIM;
    #pragma unroll
    for (int p = 0; p < 32; p += 8)
        t[threadIdx.y + p][threadIdx.x] = W[(size_t)(k0 + threadIdx.y + p) * DIM + n0 + threadIdx.x];
    __syncthreads();
    #pragma unroll
    for (int p = 0; p < 32; p += 8) {
        int n = n0 + threadIdx.y + p;
        int k = k0 + threadIdx.x;
        float v = t[threadIdx.x][threadIdx.y + p];
        uint32_t r;
        asm volatile("cvt.rna.tf32.f32 %0, %1;" : "=r"(r) : "f"(v));
        g_wt[(size_t)e * DIM * DIM + (size_t)n * DIM + k] = __uint_as_float(r);
    }
}

// ---------------- grouped GEMM ----------------
__device__ __forceinline__ void load_stage(uint32_t smem_base, int stage, int c,
                                           long tok_base, int e, int col0, int tid,
                                           const float* __restrict__ inputs) {
    const int kk = c * BK;
    const uint32_t sA = smem_base + stage * STAGE_BYTES;
    const uint32_t sB = sA + A_TILE_BYTES;
    // A: 128 m-rows x 128B data (8 x 16B chunks), stride 144B
    #pragma unroll
    for (int i = tid; i < 1024; i += 256) {
        int r = i >> 3, ch = i & 7;
        long tok = tok_base + r;
        bool v = tok < (long)NTOK;
        const float* g = inputs + (v ? ((size_t)tok * DIM + kk + ch * 4) : 0);
        cp16(sA + (uint32_t)(r * ROW_STRIDE + ch * 16), g, v);
    }
    // B: 128 n-rows x 128B data (8 x 16B chunks of k), stride 144B, from Wt[e][n][k]
    #pragma unroll
    for (int i = tid; i < 1024; i += 256) {
        int r = i >> 3, ch = i & 7;
        const float* g = g_wt + (size_t)e * DIM * DIM + (size_t)(col0 + r) * DIM + kk + ch * 4;
        cp16(sB + (uint32_t)(r * ROW_STRIDE + ch * 16), g, true);
    }
    asm volatile("cp.async.commit_group;" ::: "memory");
}

__global__ __launch_bounds__(256, 2)
void grouped_gemm(const int* __restrict__ sizes,
                  const float* __restrict__ inputs,
                  float* __restrict__ out) {
    extern __shared__ char smem[];
    const int e = blockIdx.z;
    const int size = sizes[e];
    const int row0 = blockIdx.x * BM;
    if (row0 >= size) return;
    const int col0 = blockIdx.y * BN;
    const long tok_base = (long)g_off[e] + row0;

    const uint32_t smem_base = smem_u32(smem);
    const int tid = threadIdx.x;
    const int wid = tid >> 5;
    const int lane = tid & 31;
    const int wm = wid & 3;       // 4 warps along M: 32 rows each
    const int wn = wid >> 2;      // 2 warps along N: 64 cols each
    const int g = lane >> 2;      // group 0..7
    const int t = lane & 3;       // thread-in-group 0..3

    // ldmatrix lane-address components
    const int a_row  = lane & 15;            // row within 16-row fragment
    const int a_koff = (lane >> 4) * 4;      // fp32 k-offset 0 or 4
    const int b_m    = lane >> 3;            // matrix index 0..3
    const int b_row  = ((b_m >> 1) * 8) + (lane & 7);   // n-row within 16-row pair
    const int b_koff = (b_m & 1) * 4;        // fp32 k-offset 0 or 4

    float acc[2][8][4];
    #pragma unroll
    for (int mt = 0; mt < 2; mt++)
        #pragma unroll
        for (int nt = 0; nt < 8; nt++)
            #pragma unroll
            for (int q = 0; q < 4; q++) acc[mt][nt][q] = 0.f;

    // prologue: depth-2 prefetch
    load_stage(smem_base, 0, 0, tok_base, e, col0, tid, inputs);
    load_stage(smem_base, 1, 1, tok_base, e, col0, tid, inputs);

    for (int c = 0; c < NCHUNK; c++) {
        if (c == NCHUNK - 1) asm volatile("cp.async.wait_group 0;" ::: "memory");
        else                 asm volatile("cp.async.wait_group 1;" ::: "memory");
        // single barrier: publishes chunk c AND protects stage (c+2)%3 (read in c-1)
        __syncthreads();
        if (c + 2 < NCHUNK)
            load_stage(smem_base, (c + 2) % NSTAGE, c + 2, tok_base, e, col0, tid, inputs);

        const uint32_t sA = smem_base + (c % NSTAGE) * STAGE_BYTES;
        const uint32_t sB = sA + A_TILE_BYTES;

        #pragma unroll
        for (int ks = 0; ks < 4; ks++) {
            // Batch ALL fragment loads for this k-slice up front: 2 A + 4 B ldmatrix
            // back-to-back, so the crossbar has 6 in-flight and the MMA block below
            // overlaps the load tail (scoreboard: each mma waits only on its own b).
            uint32_t a[2][4];
            uint32_t b[4][4];
            #pragma unroll
            for (int mt = 0; mt < 2; mt++) {
                uint32_t addr = sA + (uint32_t)((wm * 32 + mt * 16 + a_row) * ROW_STRIDE
                                                + (ks * 8 + a_koff) * 4);
                ldsm_x4(a[mt], addr);
            }
            #pragma unroll
            for (int p = 0; p < 4; p++) {
                uint32_t addr = sB + (uint32_t)((wn * 64 + p * 16 + b_row) * ROW_STRIDE
                                                + (ks * 8 + b_koff) * 4);
                ldsm_x4(b[p], addr);    // pre-rounded (rna) in prep_kernel
            }
            #pragma unroll
            for (int p = 0; p < 4; p++) {
                mma_tf32(acc[0][2 * p],     a[0], b[p][0], b[p][1]);
                mma_tf32(acc[1][2 * p],     a[1], b[p][0], b[p][1]);
                mma_tf32(acc[0][2 * p + 1], a[0], b[p][2], b[p][3]);
                mma_tf32(acc[1][2 * p + 1], a[1], b[p][2], b[p][3]);
            }
        }
    }

    // ---- epilogue: c0=[g][2t] c1=[g][2t+1] c2=[g+8][2t] c3=[g+8][2t+1]
    #pragma unroll
    for (int mt = 0; mt < 2; mt++) {
        int r_lo = wm * 32 + mt * 16 + g;
        int r_hi = r_lo + 8;
        bool v_lo = (row0 + r_lo) < size;
        bool v_hi = (row0 + r_hi) < size;
        float* p_lo = out + (size_t)(tok_base + r_lo) * DIM + col0;
        float* p_hi = out + (size_t)(tok_base + r_hi) * DIM + col0;
        #pragma unroll
        for (int nt = 0; nt < 8; nt++) {
            int cidx = wn * 64 + nt * 8 + t * 2;
            if (v_lo) *(float2*)(p_lo + cidx) = make_float2(acc[mt][nt][0], acc[mt][nt][1]);
            if (v_hi) *(float2*)(p_hi + cidx) = make_float2(acc[mt][nt][2], acc[mt][nt][3]);
        }
    }
}

// ---------------- launch ----------------
extern "C" void kernel_launch(void* const* d_in, const int* in_sizes, int n_in,
                              void* d_out, int out_size) {
    const float* inputs = (const float*)d_in[0];
    const int*   sizes  = (const int*)  d_in[1];
    const float* weight = (const float*)d_in[2];
    float*       out    = (float*)d_out;

    cudaFuncSetAttribute(grouped_gemm, cudaFuncAttributeMaxDynamicSharedMemorySize, SMEM_TOTAL);

    // 2 launches per call (ncu -s 5 -c 1 lands on grouped_gemm)
    prep_kernel<<<dim3(16, 16, 64), dim3(32, 8)>>>(weight, sizes);
    grouped_gemm<<<dim3(CAP / BM, DIM / BN, NUM_E), 256, SMEM_TOTAL>>>(sizes, inputs, out);
}

// round 17
// speedup vs baseline: 1.0495x; 1.0017x over previous
#include <cuda_runtime.h>
#include <cstdint>

#define NUM_E 64
#define DIM 512
#define NTOK 131072
#define CAP 3072

#define BM 128
#define BN 128
#define BK 32
#define NCHUNK 16            // 512 / 32
#define NSTAGE 3

#define ROW_STRIDE 144       // bytes per smem row: 32 fp32 = 128B data + 16 pad
#define A_TILE_BYTES (BM * ROW_STRIDE)        // 18432
#define B_TILE_BYTES (BN * ROW_STRIDE)        // 18432 (n-major: 128 n-rows x 32 k)
#define STAGE_BYTES (A_TILE_BYTES + B_TILE_BYTES)   // 36864
#define SMEM_TOTAL (NSTAGE * STAGE_BYTES)     // 110592; x2 CTAs = 221184 <= 228KB

__device__ int g_off[NUM_E];
__device__ float g_wt[(size_t)NUM_E * DIM * DIM];   // W transposed [e][n][k], tf32-rounded

// ---------------- helpers ----------------
__device__ __forceinline__ uint32_t smem_u32(const void* p) {
    uint32_t a;
    asm("{ .reg .u64 t; cvta.to.shared.u64 t, %1; cvt.u32.u64 %0, t; }" : "=r"(a) : "l"(p));
    return a;
}

__device__ __forceinline__ void cp16(uint32_t dst, const void* src, bool pred) {
    int sz = pred ? 16 : 0;
    asm volatile("cp.async.cg.shared.global [%0], [%1], 16, %2;"
        :: "r"(dst), "l"(src), "r"(sz) : "memory");
}

__device__ __forceinline__ void ldsm_x4(uint32_t* r, uint32_t addr) {
    asm volatile("ldmatrix.sync.aligned.m8n8.x4.shared.b16 {%0,%1,%2,%3}, [%4];"
        : "=r"(r[0]), "=r"(r[1]), "=r"(r[2]), "=r"(r[3]) : "r"(addr));
}

// m16n8k8 tf32: A 4 regs, B 2 regs, C 4 fp32
__device__ __forceinline__ void mma_tf32(float* c, const uint32_t* a,
                                         uint32_t b0, uint32_t b1) {
    asm volatile(
        "mma.sync.aligned.m16n8k8.row.col.f32.tf32.tf32.f32 "
        "{%0,%1,%2,%3}, {%4,%5,%6,%7}, {%8,%9}, {%0,%1,%2,%3};"
        : "+f"(c[0]), "+f"(c[1]), "+f"(c[2]), "+f"(c[3])
        : "r"(a[0]), "r"(a[1]), "r"(a[2]), "r"(a[3]), "r"(b0), "r"(b1));
}

// ---------------- prep: W transpose+round AND expert-offset scan ----------------
// W[e][k][n] fp32 -> Wt[e][n][k] tf32-rounded fp32; block (0,0,0) also scans sizes.
__global__ void prep_kernel(const float* __restrict__ w, const int* __restrict__ sizes) {
    __shared__ float t[32][33];
    const int e = blockIdx.z;
    const int k0 = blockIdx.x * 32, n0 = blockIdx.y * 32;

    if (blockIdx.x == 0 && blockIdx.y == 0 && blockIdx.z == 0 &&
        threadIdx.x == 0 && threadIdx.y == 0) {
        int acc = 0;
        #pragma unroll
        for (int i = 0; i < NUM_E; i++) { int v = sizes[i]; g_off[i] = acc; acc += v; }
    }

    const float* W = w + (size_t)e * DIM * DIM;
    #pragma unroll
    for (int p = 0; p < 32; p += 8)
        t[threadIdx.y + p][threadIdx.x] = W[(size_t)(k0 + threadIdx.y + p) * DIM + n0 + threadIdx.x];
    __syncthreads();
    #pragma unroll
    for (int p = 0; p < 32; p += 8) {
        int n = n0 + threadIdx.y + p;
        int k = k0 + threadIdx.x;
        float v = t[threadIdx.x][threadIdx.y + p];
        uint32_t r;
        asm volatile("cvt.rna.tf32.f32 %0, %1;" : "=r"(r) : "f"(v));
        g_wt[(size_t)e * DIM * DIM + (size_t)n * DIM + k] = __uint_as_float(r);
    }
}

// ---------------- grouped GEMM ----------------
__device__ __forceinline__ void load_stage(uint32_t smem_base, int stage, int c,
                                           long tok_base, int e, int col0, int tid,
                                           const float* __restrict__ inputs) {
    const int kk = c * BK;
    const uint32_t sA = smem_base + stage * STAGE_BYTES;
    const uint32_t sB = sA + A_TILE_BYTES;
    // A: 128 m-rows x 128B data (8 x 16B chunks), stride 144B
    #pragma unroll
    for (int i = tid; i < 1024; i += 256) {
        int r = i >> 3, ch = i & 7;
        long tok = tok_base + r;
        bool v = tok < (long)NTOK;
        const float* g = inputs + (v ? ((size_t)tok * DIM + kk + ch * 4) : 0);
        cp16(sA + (uint32_t)(r * ROW_STRIDE + ch * 16), g, v);
    }
    // B: 128 n-rows x 128B data (8 x 16B chunks of k), stride 144B, from Wt[e][n][k]
    #pragma unroll
    for (int i = tid; i < 1024; i += 256) {
        int r = i >> 3, ch = i & 7;
        const float* g = g_wt + (size_t)e * DIM * DIM + (size_t)(col0 + r) * DIM + kk + ch * 4;
        cp16(sB + (uint32_t)(r * ROW_STRIDE + ch * 16), g, true);
    }
    asm volatile("cp.async.commit_group;" ::: "memory");
}

__global__ __launch_bounds__(256, 2)
void grouped_gemm(const int* __restrict__ sizes,
                  const float* __restrict__ inputs,
                  float* __restrict__ out) {
    extern __shared__ char smem[];
    const int e = blockIdx.z;
    const int size = sizes[e];
    const int row0 = blockIdx.x * BM;
    if (row0 >= size) return;
    const int col0 = blockIdx.y * BN;
    const long tok_base = (long)g_off[e] + row0;

    const uint32_t smem_base = smem_u32(smem);
    const int tid = threadIdx.x;
    const int wid = tid >> 5;
    const int lane = tid & 31;
    const int wm = wid & 3;       // 4 warps along M: 32 rows each
    const int wn = wid >> 2;      // 2 warps along N: 64 cols each
    const int g = lane >> 2;      // group 0..7
    const int t = lane & 3;       // thread-in-group 0..3

    // ldmatrix lane-address components
    const int a_row  = lane & 15;            // row within 16-row fragment
    const int a_koff = (lane >> 4) * 4;      // fp32 k-offset 0 or 4
    const int b_m    = lane >> 3;            // matrix index 0..3
    const int b_row  = ((b_m >> 1) * 8) + (lane & 7);   // n-row within 16-row pair
    const int b_koff = (b_m & 1) * 4;        // fp32 k-offset 0 or 4

    float acc[2][8][4];
    #pragma unroll
    for (int mt = 0; mt < 2; mt++)
        #pragma unroll
        for (int nt = 0; nt < 8; nt++)
            #pragma unroll
            for (int q = 0; q < 4; q++) acc[mt][nt][q] = 0.f;

    // prologue: depth-2 prefetch
    load_stage(smem_base, 0, 0, tok_base, e, col0, tid, inputs);
    load_stage(smem_base, 1, 1, tok_base, e, col0, tid, inputs);

    for (int c = 0; c < NCHUNK; c++) {
        if (c == NCHUNK - 1) asm volatile("cp.async.wait_group 0;" ::: "memory");
        else                 asm volatile("cp.async.wait_group 1;" ::: "memory");
        // single barrier: publishes chunk c AND protects stage (c+2)%3 (read in c-1)
        __syncthreads();
        if (c + 2 < NCHUNK)
            load_stage(smem_base, (c + 2) % NSTAGE, c + 2, tok_base, e, col0, tid, inputs);

        const uint32_t sA = smem_base + (c % NSTAGE) * STAGE_BYTES;
        const uint32_t sB = sA + A_TILE_BYTES;

        #pragma unroll
        for (int ks = 0; ks < 4; ks++) {
            // Batch ALL fragment loads for this k-slice up front: 2 A + 4 B ldmatrix
            // back-to-back, so the crossbar has 6 in-flight and the MMA block below
            // overlaps the load tail (scoreboard: each mma waits only on its own b).
            uint32_t a[2][4];
            uint32_t b[4][4];
            #pragma unroll
            for (int mt = 0; mt < 2; mt++) {
                uint32_t addr = sA + (uint32_t)((wm * 32 + mt * 16 + a_row) * ROW_STRIDE
                                                + (ks * 8 + a_koff) * 4);
                ldsm_x4(a[mt], addr);
            }
            #pragma unroll
            for (int p = 0; p < 4; p++) {
                uint32_t addr = sB + (uint32_t)((wn * 64 + p * 16 + b_row) * ROW_STRIDE
                                                + (ks * 8 + b_koff) * 4);
                ldsm_x4(b[p], addr);    // pre-rounded (rna) in prep_kernel
            }
            #pragma unroll
            for (int p = 0; p < 4; p++) {
                mma_tf32(acc[0][2 * p],     a[0], b[p][0], b[p][1]);
                mma_tf32(acc[1][2 * p],     a[1], b[p][0], b[p][1]);
                mma_tf32(acc[0][2 * p + 1], a[0], b[p][2], b[p][3]);
                mma_tf32(acc[1][2 * p + 1], a[1], b[p][2], b[p][3]);
            }
        }
    }

    // ---- epilogue: c0=[g][2t] c1=[g][2t+1] c2=[g+8][2t] c3=[g+8][2t+1]
    #pragma unroll
    for (int mt = 0; mt < 2; mt++) {
        int r_lo = wm * 32 + mt * 16 + g;
        int r_hi = r_lo + 8;
        bool v_lo = (row0 + r_lo) < size;
        bool v_hi = (row0 + r_hi) < size;
        float* p_lo = out + (size_t)(tok_base + r_lo) * DIM + col0;
        float* p_hi = out + (size_t)(tok_base + r_hi) * DIM + col0;
        #pragma unroll
        for (int nt = 0; nt < 8; nt++) {
            int cidx = wn * 64 + nt * 8 + t * 2;
            if (v_lo) *(float2*)(p_lo + cidx) = make_float2(acc[mt][nt][0], acc[mt][nt][1]);
            if (v_hi) *(float2*)(p_hi + cidx) = make_float2(acc[mt][nt][2], acc[mt][nt][3]);
        }
    }
}

// ---------------- launch ----------------
extern "C" void kernel_launch(void* const* d_in, const int* in_sizes, int n_in,
                              void* d_out, int out_size) {
    const float* inputs = (const float*)d_in[0];
    const int*   sizes  = (const int*)  d_in[1];
    const float* weight = (const float*)d_in[2];
    float*       out    = (float*)d_out;

    cudaFuncSetAttribute(grouped_gemm, cudaFuncAttributeMaxDynamicSharedMemorySize, SMEM_TOTAL);

    // 2 launches per call (ncu -s 5 -c 1 lands on grouped_gemm)
    prep_kernel<<<dim3(16, 16, 64), dim3(32, 8)>>>(weight, sizes);
    grouped_gemm<<<dim3(CAP / BM, DIM / BN, NUM_E), 256, SMEM_TOTAL>>>(sizes, inputs, out);
}